// round 11
// baseline (speedup 1.0000x reference)
#include <cuda_runtime.h>
#include <cuda_fp16.h>

#define N_NODES 100000
#define IN_DIM  1024
#define OUT_DIM 256
#define NNZ_X   3200000
#define NNZ_ADJ 3200000

#define ELLW 128           // ELL row capacity; rows are Poisson(32), P(>=128)~0

// ---------------- scratch (__device__ globals; no allocs allowed) ----------
__device__ __half g_xw[(size_t)N_NODES * OUT_DIM];     // 51.2 MB (L2-resident)
__device__ __half g_wh[IN_DIM * OUT_DIM];              // 512 KB

// cnt arrays: zero at module load; spmm kernels reset them to 0 each replay,
// so the scatter's atomicAdd always starts from 0 (self-restoring).
__device__ int g_cnt_x[N_NODES];
__device__ int g_cnt_a[N_NODES];
__device__ int g_ell_x[(size_t)N_NODES * ELLW];        // packed (col<<16)|fp16
__device__ int g_ell_a[(size_t)N_NODES * ELLW];        // packed (col<<15)|q15

// ---------------- mixed-precision FMA: fp16 x fp16 -> fp32 accum ------------
__device__ __forceinline__ void fma_h2(float& s0, float& s1, int wpair, unsigned short vh) {
    unsigned short h0, h1;
    asm("mov.b32 {%0, %1}, %2;" : "=h"(h0), "=h"(h1) : "r"(wpair));
    asm("fma.rn.f32.f16 %0, %1, %2, %0;" : "+f"(s0) : "h"(h0), "h"(vh));
    asm("fma.rn.f32.f16 %0, %1, %2, %0;" : "+f"(s1) : "h"(h1), "h"(vh));
}

// ---------------- W fp32 -> fp16 -------------------------------------------
__global__ void wcvt_kernel(const float* __restrict__ W, __half* __restrict__ Wh) {
    int i = blockIdx.x * blockDim.x + threadIdx.x;      // over float2 pairs
    if (i < IN_DIM * OUT_DIM / 2) {
        float2 w = __ldcs(reinterpret_cast<const float2*>(W) + i);
        reinterpret_cast<__half2*>(Wh)[i] = __floats2half2_rn(w.x, w.y);
    }
}

// ---------------- one-pass COO -> ELL scatter --------------------------------
// MODE 0 (x):   col < 1024            -> p = (col<<16) | fp16(val) bits
// MODE 1 (adj): col < 2^17, val [0,1) -> p = (col<<15) | round(val*32768) clamped
template <int MODE>
__global__ void scatter_ell_kernel(const int* __restrict__ rows, const int* __restrict__ cols,
                                   const float* __restrict__ vals,
                                   int* __restrict__ cnt, int* __restrict__ ell, int nnz) {
    int i = blockIdx.x * blockDim.x + threadIdx.x;
    if (i >= nnz) return;
    int r = __ldcs(&rows[i]);
    int c = __ldcs(&cols[i]);
    float v = __ldcs(&vals[i]);
    int packed;
    if (MODE == 0) {
        packed = (c << 16) | (int)__half_as_ushort(__float2half_rn(v));
    } else {
        int q = __float2int_rn(v * 32768.f);
        q = min(q, 32767);
        packed = (c << 15) | q;
    }
    int slot = atomicAdd(&cnt[r], 1);
    if (slot < ELLW)                                   // overflow guard (never hit)
        ell[(size_t)r * ELLW + slot] = packed;
}

// ---------------- SpMM1: warp per row; ONE int4 gather + mixed FMA ----------
// Reads cnt[r] as row length, then resets it to 0 for the next graph replay.
__global__ void __launch_bounds__(256, 8)
spmm1_kernel(int* __restrict__ cnt, const int* __restrict__ ell,
             const __half* __restrict__ Wh, __half* __restrict__ xw) {
    int warp = (blockIdx.x * blockDim.x + threadIdx.x) >> 5;
    int lane = threadIdx.x & 31;
    if (warp >= N_NODES) return;

    int n = cnt[warp];
    if (lane == 0) cnt[warp] = 0;                      // self-restore for next replay
    n = min(n, ELLW);
    const int* row = ell + (size_t)warp * ELLW;

    float a0 = 0.f, a1 = 0.f, a2 = 0.f, a3 = 0.f;
    float a4 = 0.f, a5 = 0.f, a6 = 0.f, a7 = 0.f;

    for (int base = 0; base < n; base += 32) {
        int k = base + lane;
        int pk = (k < n) ? __ldcs(&row[k]) : 0;
        int m = min(32, n - base);
#pragma unroll 8
        for (int t = 0; t < m; t++) {
            int p = __shfl_sync(0xffffffffu, pk, t);
            int cc = ((unsigned)p) >> 16;
            unsigned short vh = (unsigned short)(p & 0xffff);   // fp16 bits
            int4 wv = __ldg(reinterpret_cast<const int4*>(Wh + (size_t)cc * OUT_DIM) + lane);
            fma_h2(a0, a1, wv.x, vh);
            fma_h2(a2, a3, wv.y, vh);
            fma_h2(a4, a5, wv.z, vh);
            fma_h2(a6, a7, wv.w, vh);
        }
    }

    int4 o;
    __half2 h0 = __floats2half2_rn(a0, a1);
    __half2 h1 = __floats2half2_rn(a2, a3);
    __half2 h2 = __floats2half2_rn(a4, a5);
    __half2 h3 = __floats2half2_rn(a6, a7);
    o.x = *reinterpret_cast<int*>(&h0);
    o.y = *reinterpret_cast<int*>(&h1);
    o.z = *reinterpret_cast<int*>(&h2);
    o.w = *reinterpret_cast<int*>(&h3);
    reinterpret_cast<int4*>(xw + (size_t)warp * OUT_DIM)[lane] = o;
}

// ---------------- SpMM2 + ReLU: streaming stores protect xw in L2 -----------
__global__ void __launch_bounds__(256, 8)
spmm2_kernel(int* __restrict__ cnt, const int* __restrict__ ell,
             const __half* __restrict__ xw, float* __restrict__ out) {
    int warp = (blockIdx.x * blockDim.x + threadIdx.x) >> 5;
    int lane = threadIdx.x & 31;
    if (warp >= N_NODES) return;

    int n = cnt[warp];
    if (lane == 0) cnt[warp] = 0;                      // self-restore for next replay
    n = min(n, ELLW);
    const int* row = ell + (size_t)warp * ELLW;

    float a0 = 0.f, a1 = 0.f, a2 = 0.f, a3 = 0.f;
    float a4 = 0.f, a5 = 0.f, a6 = 0.f, a7 = 0.f;

    const float QINV = 1.f / 32768.f;

    for (int base = 0; base < n; base += 32) {
        int k = base + lane;
        int pk = (k < n) ? __ldcs(&row[k]) : 0;
        int m = min(32, n - base);
#pragma unroll 8
        for (int t = 0; t < m; t++) {
            int p = __shfl_sync(0xffffffffu, pk, t);
            int cc = ((unsigned)p) >> 15;
            float vv = (float)(p & 0x7fff) * QINV;
            int4 wv = __ldg(reinterpret_cast<const int4*>(xw + (size_t)cc * OUT_DIM) + lane);
            float2 f0 = __half22float2(*reinterpret_cast<__half2*>(&wv.x));
            float2 f1 = __half22float2(*reinterpret_cast<__half2*>(&wv.y));
            float2 f2 = __half22float2(*reinterpret_cast<__half2*>(&wv.z));
            float2 f3 = __half22float2(*reinterpret_cast<__half2*>(&wv.w));
            a0 = fmaf(vv, f0.x, a0); a1 = fmaf(vv, f0.y, a1);
            a2 = fmaf(vv, f1.x, a2); a3 = fmaf(vv, f1.y, a3);
            a4 = fmaf(vv, f2.x, a4); a5 = fmaf(vv, f2.y, a5);
            a6 = fmaf(vv, f3.x, a6); a7 = fmaf(vv, f3.y, a7);
        }
    }

    float4* d = reinterpret_cast<float4*>(out + (size_t)warp * OUT_DIM) + lane * 2;
    __stcs(d,     make_float4(fmaxf(a0, 0.f), fmaxf(a1, 0.f), fmaxf(a2, 0.f), fmaxf(a3, 0.f)));
    __stcs(d + 1, make_float4(fmaxf(a4, 0.f), fmaxf(a5, 0.f), fmaxf(a6, 0.f), fmaxf(a7, 0.f)));
}

// ---------------------------------------------------------------------------
extern "C" void kernel_launch(void* const* d_in, const int* in_sizes, int n_in,
                              void* d_out, int out_size) {
    const int*   x_rows   = (const int*)  d_in[0];
    const int*   x_cols   = (const int*)  d_in[1];
    const float* x_vals   = (const float*)d_in[2];
    const int*   adj_rows = (const int*)  d_in[3];
    const int*   adj_cols = (const int*)  d_in[4];
    const float* adj_vals = (const float*)d_in[5];
    const float* W        = (const float*)d_in[6];
    float*       out      = (float*)d_out;

    __half *xw, *Wh; int *cntx, *cnta, *ellx, *ella;
    cudaGetSymbolAddress((void**)&xw,   g_xw);
    cudaGetSymbolAddress((void**)&Wh,   g_wh);
    cudaGetSymbolAddress((void**)&cntx, g_cnt_x);
    cudaGetSymbolAddress((void**)&cnta, g_cnt_a);
    cudaGetSymbolAddress((void**)&ellx, g_ell_x);
    cudaGetSymbolAddress((void**)&ella, g_ell_a);

    // Side stream + events: created once on first (uncaptured) call, reused.
    static cudaStream_t s2 = nullptr;
    static cudaEvent_t  evFork = nullptr, evJoin = nullptr, evW = nullptr;
    if (s2 == nullptr) {
        cudaStreamCreateWithFlags(&s2, cudaStreamNonBlocking);
        cudaEventCreateWithFlags(&evFork, cudaEventDisableTiming);
        cudaEventCreateWithFlags(&evJoin, cudaEventDisableTiming);
        cudaEventCreateWithFlags(&evW,    cudaEventDisableTiming);
    }

    const int nnz_blocks = (NNZ_X + 255) / 256;

    // ---- fork ----
    cudaEventRecord(evFork, 0);
    cudaStreamWaitEvent(s2, evFork, 0);

    // ---- chain B (W convert + adj ELL build) on side stream ----
    wcvt_kernel<<<(IN_DIM * OUT_DIM / 2 + 255) / 256, 256, 0, s2>>>(W, Wh);
    cudaEventRecord(evW, s2);                       // spmm1 depends on Wh
    scatter_ell_kernel<1><<<nnz_blocks, 256, 0, s2>>>(adj_rows, adj_cols, adj_vals,
                                                      cnta, ella, NNZ_ADJ);
    cudaEventRecord(evJoin, s2);

    // ---- chain A (x ELL build + spmm1) on main stream ----
    scatter_ell_kernel<0><<<nnz_blocks, 256>>>(x_rows, x_cols, x_vals,
                                               cntx, ellx, NNZ_X);
    cudaStreamWaitEvent(0, evW, 0);                 // ensure Wh ready
    const int spmm_blocks = (N_NODES * 32 + 255) / 256;   // warp per row
    spmm1_kernel<<<spmm_blocks, 256>>>(cntx, ellx, Wh, xw);

    // ---- join, then SpMM2 + ReLU ----
    cudaStreamWaitEvent(0, evJoin, 0);
    spmm2_kernel<<<spmm_blocks, 256>>>(cnta, ella, xw, out);
}

// round 12
// speedup vs baseline: 1.5396x; 1.5396x over previous
#include <cuda_runtime.h>
#include <cuda_fp16.h>

#define N_NODES 100000
#define IN_DIM  1024
#define OUT_DIM 256
#define NNZ_X   3200000
#define NNZ_ADJ 3200000

#define SCAN_B    1024
#define N_SCANBLK ((N_NODES + SCAN_B - 1) / SCAN_B)   // 98

// ---------------- scratch (__device__ globals; no allocs allowed) ----------
__device__ __half g_xw[(size_t)N_NODES * OUT_DIM];     // 51.2 MB (L2-resident)
__device__ __half g_wh[IN_DIM * OUT_DIM];              // 512 KB

// Counters rely on zero-init at module load + self-restoring property:
// hist adds each node's count, scatter atomicSub's it back to exactly 0.
__device__ int   g_counts_x[N_NODES];
__device__ int   g_counts_a[N_NODES];
__device__ int   g_offs_x[N_NODES + 1];
__device__ int   g_offs_a[N_NODES + 1];
__device__ int   g_bsums_x[N_SCANBLK];
__device__ int   g_bsums_a[N_SCANBLK];
__device__ int   g_cx[NNZ_X];                          // packed (col<<16)|fp16
__device__ int   g_ca[NNZ_ADJ];                        // packed (col<<15)|q15

// ---------------- mixed-precision FMA: fp16 x fp16 -> fp32 accum ------------
__device__ __forceinline__ void fma_h2(float& s0, float& s1, int wpair, unsigned short vh) {
    unsigned short h0, h1;
    asm("mov.b32 {%0, %1}, %2;" : "=h"(h0), "=h"(h1) : "r"(wpair));
    asm("fma.rn.f32.f16 %0, %1, %2, %0;" : "+f"(s0) : "h"(h0), "h"(vh));
    asm("fma.rn.f32.f16 %0, %1, %2, %0;" : "+f"(s1) : "h"(h1), "h"(vh));
}

// ---------------- W fp32 -> fp16 -------------------------------------------
__global__ void wcvt_kernel(const float* __restrict__ W, __half* __restrict__ Wh) {
    int i = blockIdx.x * blockDim.x + threadIdx.x;      // over float2 pairs
    if (i < IN_DIM * OUT_DIM / 2) {
        float2 w = __ldcs(reinterpret_cast<const float2*>(W) + i);
        reinterpret_cast<__half2*>(Wh)[i] = __floats2half2_rn(w.x, w.y);
    }
}

// ---------------- histogram of one row array --------------------------------
__global__ void hist_kernel(const int* __restrict__ rows, int* __restrict__ counts, int nnz) {
    int i = blockIdx.x * blockDim.x + threadIdx.x;
    if (i < nnz) atomicAdd(&counts[__ldcs(&rows[i])], 1);
}

// ---------------- scan A: per-block exclusive scan --------------------------
__global__ void scanA_kernel(const int* __restrict__ counts,
                             int* __restrict__ offs, int* __restrict__ bsums) {
    __shared__ int sm[SCAN_B];
    int t = threadIdx.x;
    int i = blockIdx.x * SCAN_B + t;
    int v = (i < N_NODES) ? counts[i] : 0;
    sm[t] = v;
    __syncthreads();
    for (int d = 1; d < SCAN_B; d <<= 1) {
        int add = (t >= d) ? sm[t - d] : 0;
        __syncthreads();
        sm[t] += add;
        __syncthreads();
    }
    int incl = sm[t];
    if (i < N_NODES) offs[i] = incl - v;
    if (t == SCAN_B - 1) bsums[blockIdx.x] = incl;     // inclusive block total
}

// ---------------- scan C: re-scan block sums in-block, add offsets ----------
__global__ void scanC_kernel(int* __restrict__ offs, const int* __restrict__ bsums, int total) {
    __shared__ int sb[128];
    int t = threadIdx.x;
    if (t < 128) sb[t] = (t < N_SCANBLK) ? bsums[t] : 0;
    __syncthreads();
    for (int d = 1; d < 128; d <<= 1) {
        int add = (t < 128 && t >= d) ? sb[t - d] : 0;
        __syncthreads();
        if (t < 128) sb[t] += add;
        __syncthreads();
    }
    int boff = (blockIdx.x == 0) ? 0 : sb[blockIdx.x - 1];
    int i = blockIdx.x * SCAN_B + t;
    if (i < N_NODES) offs[i] += boff;
    if (i == 0) offs[N_NODES] = total;
}

// ---------------- scatter COO -> CSR, packed payload -------------------------
// MODE 0 (x):   col < 1024   -> p = (col<<16) | fp16(val) bits
// MODE 1 (adj): col < 2^17, val in [0,1) -> p = (col<<15) | round(val*32768) clamped
template <int MODE>
__global__ void scatter_kernel(const int* __restrict__ rows, const int* __restrict__ cols,
                               const float* __restrict__ vals,
                               const int* __restrict__ offs, int* __restrict__ cnt,
                               int* __restrict__ cdata, int nnz) {
    int i = blockIdx.x * blockDim.x + threadIdx.x;
    if (i >= nnz) return;
    int r = __ldcs(&rows[i]);
    int c = __ldcs(&cols[i]);
    float v = __ldcs(&vals[i]);
    int p = offs[r] + atomicSub(&cnt[r], 1) - 1;
    int packed;
    if (MODE == 0) {
        packed = (c << 16) | (int)__half_as_ushort(__float2half_rn(v));
    } else {
        int q = __float2int_rn(v * 32768.f);
        q = min(q, 32767);
        packed = (c << 15) | q;
    }
    cdata[p] = packed;
}

// ---------------- SpMM1 body: one nnz step ----------------------------------
#define SPMM1_STEP(PK, T)                                                        \
    {                                                                            \
        int p = __shfl_sync(0xffffffffu, (PK), (T));                             \
        int cc = ((unsigned)p) >> 16;                                            \
        unsigned short vh = (unsigned short)(p & 0xffff);                        \
        int4 wv = __ldg(reinterpret_cast<const int4*>(Wh + (size_t)cc * OUT_DIM) + lane); \
        fma_h2(a0, a1, wv.x, vh);                                                \
        fma_h2(a2, a3, wv.y, vh);                                                \
        fma_h2(a4, a5, wv.z, vh);                                                \
        fma_h2(a6, a7, wv.w, vh);                                                \
    }

// ---------------- SpMM1: warp per row; constant-trip fast path ---------------
__global__ void __launch_bounds__(256, 8)
spmm1_kernel(const int* __restrict__ offs, const int* __restrict__ cdata,
             const __half* __restrict__ Wh, __half* __restrict__ xw) {
    int warp = (blockIdx.x * blockDim.x + threadIdx.x) >> 5;
    int lane = threadIdx.x & 31;
    if (warp >= N_NODES) return;

    int beg = offs[warp];
    int end = offs[warp + 1];

    float a0 = 0.f, a1 = 0.f, a2 = 0.f, a3 = 0.f;
    float a4 = 0.f, a5 = 0.f, a6 = 0.f, a7 = 0.f;

    for (int base = beg; base < end; base += 32) {
        int k = base + lane;
        int pk = (k < end) ? __ldcs(&cdata[k]) : 0;
        if (end - base >= 32) {
#pragma unroll
            for (int t = 0; t < 32; t++) SPMM1_STEP(pk, t)
        } else {
            int m = end - base;
            for (int t = 0; t < m; t++) SPMM1_STEP(pk, t)
        }
    }

    int4 o;
    __half2 h0 = __floats2half2_rn(a0, a1);
    __half2 h1 = __floats2half2_rn(a2, a3);
    __half2 h2 = __floats2half2_rn(a4, a5);
    __half2 h3 = __floats2half2_rn(a6, a7);
    o.x = *reinterpret_cast<int*>(&h0);
    o.y = *reinterpret_cast<int*>(&h1);
    o.z = *reinterpret_cast<int*>(&h2);
    o.w = *reinterpret_cast<int*>(&h3);
    reinterpret_cast<int4*>(xw + (size_t)warp * OUT_DIM)[lane] = o;
}

// ---------------- SpMM2 body: one nnz step -----------------------------------
#define SPMM2_STEP(PK, T)                                                        \
    {                                                                            \
        int p = __shfl_sync(0xffffffffu, (PK), (T));                             \
        int cc = ((unsigned)p) >> 15;                                            \
        float vv = (float)(p & 0x7fff) * QINV;                                   \
        int4 wv = __ldg(reinterpret_cast<const int4*>(xw + (size_t)cc * OUT_DIM) + lane); \
        float2 f0 = __half22float2(*reinterpret_cast<__half2*>(&wv.x));          \
        float2 f1 = __half22float2(*reinterpret_cast<__half2*>(&wv.y));          \
        float2 f2 = __half22float2(*reinterpret_cast<__half2*>(&wv.z));          \
        float2 f3 = __half22float2(*reinterpret_cast<__half2*>(&wv.w));          \
        a0 = fmaf(vv, f0.x, a0); a1 = fmaf(vv, f0.y, a1);                        \
        a2 = fmaf(vv, f1.x, a2); a3 = fmaf(vv, f1.y, a3);                        \
        a4 = fmaf(vv, f2.x, a4); a5 = fmaf(vv, f2.y, a5);                        \
        a6 = fmaf(vv, f3.x, a6); a7 = fmaf(vv, f3.y, a7);                        \
    }

// ---------------- SpMM2 + ReLU: constant-trip fast path ----------------------
__global__ void __launch_bounds__(256, 8)
spmm2_kernel(const int* __restrict__ offs, const int* __restrict__ cdata,
             const __half* __restrict__ xw, float* __restrict__ out) {
    int warp = (blockIdx.x * blockDim.x + threadIdx.x) >> 5;
    int lane = threadIdx.x & 31;
    if (warp >= N_NODES) return;

    int beg = offs[warp];
    int end = offs[warp + 1];

    float a0 = 0.f, a1 = 0.f, a2 = 0.f, a3 = 0.f;
    float a4 = 0.f, a5 = 0.f, a6 = 0.f, a7 = 0.f;

    const float QINV = 1.f / 32768.f;

    for (int base = beg; base < end; base += 32) {
        int k = base + lane;
        int pk = (k < end) ? __ldcs(&cdata[k]) : 0;
        if (end - base >= 32) {
#pragma unroll
            for (int t = 0; t < 32; t++) SPMM2_STEP(pk, t)
        } else {
            int m = end - base;
            for (int t = 0; t < m; t++) SPMM2_STEP(pk, t)
        }
    }

    float4* d = reinterpret_cast<float4*>(out + (size_t)warp * OUT_DIM) + lane * 2;
    __stcs(d,     make_float4(fmaxf(a0, 0.f), fmaxf(a1, 0.f), fmaxf(a2, 0.f), fmaxf(a3, 0.f)));
    __stcs(d + 1, make_float4(fmaxf(a4, 0.f), fmaxf(a5, 0.f), fmaxf(a6, 0.f), fmaxf(a7, 0.f)));
}

// ---------------------------------------------------------------------------
extern "C" void kernel_launch(void* const* d_in, const int* in_sizes, int n_in,
                              void* d_out, int out_size) {
    const int*   x_rows   = (const int*)  d_in[0];
    const int*   x_cols   = (const int*)  d_in[1];
    const float* x_vals   = (const float*)d_in[2];
    const int*   adj_rows = (const int*)  d_in[3];
    const int*   adj_cols = (const int*)  d_in[4];
    const float* adj_vals = (const float*)d_in[5];
    const float* W        = (const float*)d_in[6];
    float*       out      = (float*)d_out;

    __half *xw, *Wh; int *cntx, *cnta, *ox, *oa, *bx, *ba, *cx, *ca;
    cudaGetSymbolAddress((void**)&xw,   g_xw);
    cudaGetSymbolAddress((void**)&Wh,   g_wh);
    cudaGetSymbolAddress((void**)&cntx, g_counts_x);
    cudaGetSymbolAddress((void**)&cnta, g_counts_a);
    cudaGetSymbolAddress((void**)&ox,   g_offs_x);
    cudaGetSymbolAddress((void**)&oa,   g_offs_a);
    cudaGetSymbolAddress((void**)&bx,   g_bsums_x);
    cudaGetSymbolAddress((void**)&ba,   g_bsums_a);
    cudaGetSymbolAddress((void**)&cx,   g_cx);
    cudaGetSymbolAddress((void**)&ca,   g_ca);

    // Side stream + events: created once on first (uncaptured) call, reused.
    static cudaStream_t s2 = nullptr;
    static cudaEvent_t  evFork = nullptr, evJoin = nullptr, evW = nullptr;
    if (s2 == nullptr) {
        cudaStreamCreateWithFlags(&s2, cudaStreamNonBlocking);
        cudaEventCreateWithFlags(&evFork, cudaEventDisableTiming);
        cudaEventCreateWithFlags(&evJoin, cudaEventDisableTiming);
        cudaEventCreateWithFlags(&evW,    cudaEventDisableTiming);
    }

    const int nnz_blocks = (NNZ_X + 255) / 256;

    // ---- fork (counters are self-zeroed; no zero pass needed) ----
    cudaEventRecord(evFork, 0);
    cudaStreamWaitEvent(s2, evFork, 0);

    // ---- chain B (W convert + adj build) on side stream ----
    wcvt_kernel<<<(IN_DIM * OUT_DIM / 2 + 255) / 256, 256, 0, s2>>>(W, Wh);
    cudaEventRecord(evW, s2);                       // spmm1 depends on Wh
    hist_kernel<<<nnz_blocks, 256, 0, s2>>>(adj_rows, cnta, NNZ_ADJ);
    scanA_kernel<<<N_SCANBLK, SCAN_B, 0, s2>>>(cnta, oa, ba);
    scanC_kernel<<<N_SCANBLK, SCAN_B, 0, s2>>>(oa, ba, NNZ_ADJ);
    scatter_kernel<1><<<nnz_blocks, 256, 0, s2>>>(adj_rows, adj_cols, adj_vals,
                                                  oa, cnta, ca, NNZ_ADJ);
    cudaEventRecord(evJoin, s2);

    // ---- chain A (x build + spmm1) on main stream ----
    hist_kernel<<<nnz_blocks, 256>>>(x_rows, cntx, NNZ_X);
    scanA_kernel<<<N_SCANBLK, SCAN_B>>>(cntx, ox, bx);
    scanC_kernel<<<N_SCANBLK, SCAN_B>>>(ox, bx, NNZ_X);
    scatter_kernel<0><<<nnz_blocks, 256>>>(x_rows, x_cols, x_vals,
                                           ox, cntx, cx, NNZ_X);

    cudaStreamWaitEvent(0, evW, 0);                 // ensure Wh ready
    const int spmm_blocks = (N_NODES * 32 + 255) / 256;   // warp per row
    spmm1_kernel<<<spmm_blocks, 256>>>(ox, cx, Wh, xw);

    // ---- join, then SpMM2 + ReLU ----
    cudaStreamWaitEvent(0, evJoin, 0);
    spmm2_kernel<<<spmm_blocks, 256>>>(oa, ca, xw, out);
}

// round 13
// speedup vs baseline: 1.6031x; 1.0412x over previous
#include <cuda_runtime.h>
#include <cuda_fp16.h>

#define N_NODES 100000
#define IN_DIM  1024
#define OUT_DIM 256
#define NNZ_X   3200000
#define NNZ_ADJ 3200000

#define SCAN_B    1024
#define N_SCANBLK ((N_NODES + SCAN_B - 1) / SCAN_B)   // 98

// ---------------- scratch (__device__ globals; no allocs allowed) ----------
__device__ __half g_xw[(size_t)N_NODES * OUT_DIM];     // 51.2 MB (L2-resident)
__device__ __half g_wh[IN_DIM * OUT_DIM];              // 512 KB

// Counters rely on zero-init at module load + self-restoring property:
// hist adds each node's count, scatter atomicSub's it back to exactly 0.
__device__ int   g_counts_x[N_NODES];
__device__ int   g_counts_a[N_NODES];
__device__ int   g_offs_x[N_NODES + 1];
__device__ int   g_offs_a[N_NODES + 1];
__device__ int   g_bsums_x[N_SCANBLK];
__device__ int   g_bsums_a[N_SCANBLK];
__device__ int   g_cx[NNZ_X];                          // packed (col<<16)|fp16
__device__ int   g_ca[NNZ_ADJ];                        // packed (col<<15)|q15

// ---------------- mixed-precision FMA: fp16 x fp16 -> fp32 accum ------------
__device__ __forceinline__ void fma_h2(float& s0, float& s1, int wpair, unsigned short vh) {
    unsigned short h0, h1;
    asm("mov.b32 {%0, %1}, %2;" : "=h"(h0), "=h"(h1) : "r"(wpair));
    asm("fma.rn.f32.f16 %0, %1, %2, %0;" : "+f"(s0) : "h"(h0), "h"(vh));
    asm("fma.rn.f32.f16 %0, %1, %2, %0;" : "+f"(s1) : "h"(h1), "h"(vh));
}

// ---------------- W fp32 -> fp16 -------------------------------------------
__global__ void wcvt_kernel(const float* __restrict__ W, __half* __restrict__ Wh) {
    int i = blockIdx.x * blockDim.x + threadIdx.x;      // over float2 pairs
    if (i < IN_DIM * OUT_DIM / 2) {
        float2 w = __ldcs(reinterpret_cast<const float2*>(W) + i);
        reinterpret_cast<__half2*>(Wh)[i] = __floats2half2_rn(w.x, w.y);
    }
}

// ---------------- histogram of one row array --------------------------------
__global__ void hist_kernel(const int* __restrict__ rows, int* __restrict__ counts, int nnz) {
    int i = blockIdx.x * blockDim.x + threadIdx.x;
    if (i < nnz) atomicAdd(&counts[__ldcs(&rows[i])], 1);
}

// ---------------- scan A: per-block exclusive scan --------------------------
__global__ void scanA_kernel(const int* __restrict__ counts,
                             int* __restrict__ offs, int* __restrict__ bsums) {
    __shared__ int sm[SCAN_B];
    int t = threadIdx.x;
    int i = blockIdx.x * SCAN_B + t;
    int v = (i < N_NODES) ? counts[i] : 0;
    sm[t] = v;
    __syncthreads();
    for (int d = 1; d < SCAN_B; d <<= 1) {
        int add = (t >= d) ? sm[t - d] : 0;
        __syncthreads();
        sm[t] += add;
        __syncthreads();
    }
    int incl = sm[t];
    if (i < N_NODES) offs[i] = incl - v;
    if (t == SCAN_B - 1) bsums[blockIdx.x] = incl;     // inclusive block total
}

// ---------------- scan C: re-scan block sums in-block, add offsets ----------
__global__ void scanC_kernel(int* __restrict__ offs, const int* __restrict__ bsums, int total) {
    __shared__ int sb[128];
    int t = threadIdx.x;
    if (t < 128) sb[t] = (t < N_SCANBLK) ? bsums[t] : 0;
    __syncthreads();
    for (int d = 1; d < 128; d <<= 1) {
        int add = (t < 128 && t >= d) ? sb[t - d] : 0;
        __syncthreads();
        if (t < 128) sb[t] += add;
        __syncthreads();
    }
    int boff = (blockIdx.x == 0) ? 0 : sb[blockIdx.x - 1];
    int i = blockIdx.x * SCAN_B + t;
    if (i < N_NODES) offs[i] += boff;
    if (i == 0) offs[N_NODES] = total;
}

// ---------------- scatter COO -> CSR, packed payload -------------------------
// MODE 0 (x):   col < 1024   -> p = (col<<16) | fp16(val) bits
// MODE 1 (adj): col < 2^17, val in [0,1) -> p = (col<<15) | round(val*32768) clamped
template <int MODE>
__global__ void scatter_kernel(const int* __restrict__ rows, const int* __restrict__ cols,
                               const float* __restrict__ vals,
                               const int* __restrict__ offs, int* __restrict__ cnt,
                               int* __restrict__ cdata, int nnz) {
    int i = blockIdx.x * blockDim.x + threadIdx.x;
    if (i >= nnz) return;
    int r = __ldcs(&rows[i]);
    int c = __ldcs(&cols[i]);
    float v = __ldcs(&vals[i]);
    int p = offs[r] + atomicSub(&cnt[r], 1) - 1;
    int packed;
    if (MODE == 0) {
        packed = (c << 16) | (int)__half_as_ushort(__float2half_rn(v));
    } else {
        int q = __float2int_rn(v * 32768.f);
        q = min(q, 32767);
        packed = (c << 15) | q;
    }
    cdata[p] = packed;
}

// ---------------- SpMM1 step: uniform scalar payload load (no shfl) ---------
#define SPMM1_STEP(IDX)                                                          \
    {                                                                            \
        int p = __ldg(&cdata[(IDX)]);   /* all lanes same addr -> broadcast */   \
        int cc = ((unsigned)p) >> 16;                                            \
        unsigned short vh = (unsigned short)(p & 0xffff);                        \
        int4 wv = __ldg(reinterpret_cast<const int4*>(Wh + (size_t)cc * OUT_DIM) + lane); \
        fma_h2(a0, a1, wv.x, vh);                                                \
        fma_h2(a2, a3, wv.y, vh);                                                \
        fma_h2(a4, a5, wv.z, vh);                                                \
        fma_h2(a6, a7, wv.w, vh);                                                \
    }

// ---------------- SpMM1: warp per row --------------------------------------
__global__ void __launch_bounds__(256, 8)
spmm1_kernel(const int* __restrict__ offs, const int* __restrict__ cdata,
             const __half* __restrict__ Wh, __half* __restrict__ xw) {
    int warp = (blockIdx.x * blockDim.x + threadIdx.x) >> 5;
    int lane = threadIdx.x & 31;
    if (warp >= N_NODES) return;

    int beg = offs[warp];
    int end = offs[warp + 1];

    float a0 = 0.f, a1 = 0.f, a2 = 0.f, a3 = 0.f;
    float a4 = 0.f, a5 = 0.f, a6 = 0.f, a7 = 0.f;

    int base = beg;
    for (; base + 32 <= end; base += 32) {
#pragma unroll
        for (int t = 0; t < 32; t++) SPMM1_STEP(base + t)
    }
    for (; base < end; base++) SPMM1_STEP(base)

    int4 o;
    __half2 h0 = __floats2half2_rn(a0, a1);
    __half2 h1 = __floats2half2_rn(a2, a3);
    __half2 h2 = __floats2half2_rn(a4, a5);
    __half2 h3 = __floats2half2_rn(a6, a7);
    o.x = *reinterpret_cast<int*>(&h0);
    o.y = *reinterpret_cast<int*>(&h1);
    o.z = *reinterpret_cast<int*>(&h2);
    o.w = *reinterpret_cast<int*>(&h3);
    reinterpret_cast<int4*>(xw + (size_t)warp * OUT_DIM)[lane] = o;
}

// ---------------- SpMM2 step: uniform scalar payload load (no shfl) ---------
#define SPMM2_STEP(IDX)                                                          \
    {                                                                            \
        int p = __ldg(&cdata[(IDX)]);                                            \
        int cc = ((unsigned)p) >> 15;                                            \
        float vv = (float)(p & 0x7fff) * QINV;                                   \
        int4 wv = __ldg(reinterpret_cast<const int4*>(xw + (size_t)cc * OUT_DIM) + lane); \
        float2 f0 = __half22float2(*reinterpret_cast<__half2*>(&wv.x));          \
        float2 f1 = __half22float2(*reinterpret_cast<__half2*>(&wv.y));          \
        float2 f2 = __half22float2(*reinterpret_cast<__half2*>(&wv.z));          \
        float2 f3 = __half22float2(*reinterpret_cast<__half2*>(&wv.w));          \
        a0 = fmaf(vv, f0.x, a0); a1 = fmaf(vv, f0.y, a1);                        \
        a2 = fmaf(vv, f1.x, a2); a3 = fmaf(vv, f1.y, a3);                        \
        a4 = fmaf(vv, f2.x, a4); a5 = fmaf(vv, f2.y, a5);                        \
        a6 = fmaf(vv, f3.x, a6); a7 = fmaf(vv, f3.y, a7);                        \
    }

// ---------------- SpMM2 + ReLU ----------------------------------------------
__global__ void __launch_bounds__(256, 8)
spmm2_kernel(const int* __restrict__ offs, const int* __restrict__ cdata,
             const __half* __restrict__ xw, float* __restrict__ out) {
    int warp = (blockIdx.x * blockDim.x + threadIdx.x) >> 5;
    int lane = threadIdx.x & 31;
    if (warp >= N_NODES) return;

    int beg = offs[warp];
    int end = offs[warp + 1];

    float a0 = 0.f, a1 = 0.f, a2 = 0.f, a3 = 0.f;
    float a4 = 0.f, a5 = 0.f, a6 = 0.f, a7 = 0.f;

    const float QINV = 1.f / 32768.f;

    int base = beg;
    for (; base + 32 <= end; base += 32) {
#pragma unroll
        for (int t = 0; t < 32; t++) SPMM2_STEP(base + t)
    }
    for (; base < end; base++) SPMM2_STEP(base)

    float4* d = reinterpret_cast<float4*>(out + (size_t)warp * OUT_DIM) + lane * 2;
    __stcs(d,     make_float4(fmaxf(a0, 0.f), fmaxf(a1, 0.f), fmaxf(a2, 0.f), fmaxf(a3, 0.f)));
    __stcs(d + 1, make_float4(fmaxf(a4, 0.f), fmaxf(a5, 0.f), fmaxf(a6, 0.f), fmaxf(a7, 0.f)));
}

// ---------------------------------------------------------------------------
extern "C" void kernel_launch(void* const* d_in, const int* in_sizes, int n_in,
                              void* d_out, int out_size) {
    const int*   x_rows   = (const int*)  d_in[0];
    const int*   x_cols   = (const int*)  d_in[1];
    const float* x_vals   = (const float*)d_in[2];
    const int*   adj_rows = (const int*)  d_in[3];
    const int*   adj_cols = (const int*)  d_in[4];
    const float* adj_vals = (const float*)d_in[5];
    const float* W        = (const float*)d_in[6];
    float*       out      = (float*)d_out;

    __half *xw, *Wh; int *cntx, *cnta, *ox, *oa, *bx, *ba, *cx, *ca;
    cudaGetSymbolAddress((void**)&xw,   g_xw);
    cudaGetSymbolAddress((void**)&Wh,   g_wh);
    cudaGetSymbolAddress((void**)&cntx, g_counts_x);
    cudaGetSymbolAddress((void**)&cnta, g_counts_a);
    cudaGetSymbolAddress((void**)&ox,   g_offs_x);
    cudaGetSymbolAddress((void**)&oa,   g_offs_a);
    cudaGetSymbolAddress((void**)&bx,   g_bsums_x);
    cudaGetSymbolAddress((void**)&ba,   g_bsums_a);
    cudaGetSymbolAddress((void**)&cx,   g_cx);
    cudaGetSymbolAddress((void**)&ca,   g_ca);

    // Side stream + events: created once on first (uncaptured) call, reused.
    static cudaStream_t s2 = nullptr;
    static cudaEvent_t  evFork = nullptr, evJoin = nullptr, evW = nullptr;
    if (s2 == nullptr) {
        cudaStreamCreateWithFlags(&s2, cudaStreamNonBlocking);
        cudaEventCreateWithFlags(&evFork, cudaEventDisableTiming);
        cudaEventCreateWithFlags(&evJoin, cudaEventDisableTiming);
        cudaEventCreateWithFlags(&evW,    cudaEventDisableTiming);
    }

    const int nnz_blocks = (NNZ_X + 255) / 256;

    // ---- fork (counters are self-zeroed; no zero pass needed) ----
    cudaEventRecord(evFork, 0);
    cudaStreamWaitEvent(s2, evFork, 0);

    // ---- chain B (W convert + adj build) on side stream ----
    wcvt_kernel<<<(IN_DIM * OUT_DIM / 2 + 255) / 256, 256, 0, s2>>>(W, Wh);
    cudaEventRecord(evW, s2);                       // spmm1 depends on Wh
    hist_kernel<<<nnz_blocks, 256, 0, s2>>>(adj_rows, cnta, NNZ_ADJ);
    scanA_kernel<<<N_SCANBLK, SCAN_B, 0, s2>>>(cnta, oa, ba);
    scanC_kernel<<<N_SCANBLK, SCAN_B, 0, s2>>>(oa, ba, NNZ_ADJ);
    scatter_kernel<1><<<nnz_blocks, 256, 0, s2>>>(adj_rows, adj_cols, adj_vals,
                                                  oa, cnta, ca, NNZ_ADJ);
    cudaEventRecord(evJoin, s2);

    // ---- chain A (x build + spmm1) on main stream ----
    hist_kernel<<<nnz_blocks, 256>>>(x_rows, cntx, NNZ_X);
    scanA_kernel<<<N_SCANBLK, SCAN_B>>>(cntx, ox, bx);
    scanC_kernel<<<N_SCANBLK, SCAN_B>>>(ox, bx, NNZ_X);
    scatter_kernel<0><<<nnz_blocks, 256>>>(x_rows, x_cols, x_vals,
                                           ox, cntx, cx, NNZ_X);

    cudaStreamWaitEvent(0, evW, 0);                 // ensure Wh ready
    const int spmm_blocks = (N_NODES * 32 + 255) / 256;   // warp per row
    spmm1_kernel<<<spmm_blocks, 256>>>(ox, cx, Wh, xw);

    // ---- join, then SpMM2 + ReLU ----
    cudaStreamWaitEvent(0, evJoin, 0);
    spmm2_kernel<<<spmm_blocks, 256>>>(oa, ca, xw, out);
}

// round 14
// speedup vs baseline: 1.6039x; 1.0005x over previous
#include <cuda_runtime.h>
#include <cuda_fp16.h>

#define N_NODES 100000
#define IN_DIM  1024
#define OUT_DIM 256
#define NNZ_X   3200000
#define NNZ_ADJ 3200000

#define SCAN_B    1024
#define N_SCANBLK ((N_NODES + SCAN_B - 1) / SCAN_B)   // 98

// ---------------- scratch (__device__ globals; no allocs allowed) ----------
__device__ __half g_xw[(size_t)N_NODES * OUT_DIM];     // 51.2 MB (L2-resident)
__device__ __half g_wh[IN_DIM * OUT_DIM];              // 512 KB

// Counters rely on zero-init at module load + self-restoring property:
// hist adds each node's count, scatter atomicSub's it back to exactly 0.
__device__ int   g_counts_x[N_NODES];
__device__ int   g_counts_a[N_NODES];
__device__ int   g_offs_x[N_NODES + 1];
__device__ int   g_offs_a[N_NODES + 1];
__device__ int   g_bsums_x[N_SCANBLK];
__device__ int   g_bsums_a[N_SCANBLK];
__device__ int   g_cx[NNZ_X];                          // packed (col<<16)|fp16
__device__ int   g_ca[NNZ_ADJ];                        // packed (col<<15)|q15

// ---------------- mixed-precision FMA: fp16 x fp16 -> fp32 accum ------------
__device__ __forceinline__ void fma_h2(float& s0, float& s1, int wpair, unsigned short vh) {
    unsigned short h0, h1;
    asm("mov.b32 {%0, %1}, %2;" : "=h"(h0), "=h"(h1) : "r"(wpair));
    asm("fma.rn.f32.f16 %0, %1, %2, %0;" : "+f"(s0) : "h"(h0), "h"(vh));
    asm("fma.rn.f32.f16 %0, %1, %2, %0;" : "+f"(s1) : "h"(h1), "h"(vh));
}

// ---------------- W fp32 -> fp16 -------------------------------------------
__global__ void wcvt_kernel(const float* __restrict__ W, __half* __restrict__ Wh) {
    int i = blockIdx.x * blockDim.x + threadIdx.x;      // over float2 pairs
    if (i < IN_DIM * OUT_DIM / 2) {
        float2 w = __ldcs(reinterpret_cast<const float2*>(W) + i);
        reinterpret_cast<__half2*>(Wh)[i] = __floats2half2_rn(w.x, w.y);
    }
}

// ---------------- histogram: int4-vectorized, 4 nnz per thread --------------
__global__ void hist_kernel(const int4* __restrict__ rows4, int* __restrict__ counts, int n4) {
    int i = blockIdx.x * blockDim.x + threadIdx.x;
    if (i < n4) {
        int4 r = __ldcs(&rows4[i]);
        atomicAdd(&counts[r.x], 1);
        atomicAdd(&counts[r.y], 1);
        atomicAdd(&counts[r.z], 1);
        atomicAdd(&counts[r.w], 1);
    }
}

// ---------------- scan A: two-level warp-shuffle exclusive scan --------------
__global__ void scanA_kernel(const int* __restrict__ counts,
                             int* __restrict__ offs, int* __restrict__ bsums) {
    __shared__ int wsum[32];
    int t = threadIdx.x, lane = t & 31, wid = t >> 5;
    int i = blockIdx.x * SCAN_B + t;
    int v = (i < N_NODES) ? counts[i] : 0;
    int s = v;
#pragma unroll
    for (int d = 1; d < 32; d <<= 1) {
        int u = __shfl_up_sync(0xffffffffu, s, d);
        if (lane >= d) s += u;
    }
    if (lane == 31) wsum[wid] = s;
    __syncthreads();
    if (wid == 0) {
        int ws = wsum[lane];
#pragma unroll
        for (int d = 1; d < 32; d <<= 1) {
            int u = __shfl_up_sync(0xffffffffu, ws, d);
            if (lane >= d) ws += u;
        }
        wsum[lane] = ws;
    }
    __syncthreads();
    int incl = s + (wid ? wsum[wid - 1] : 0);
    if (i < N_NODES) offs[i] = incl - v;                // exclusive
    if (t == SCAN_B - 1) bsums[blockIdx.x] = incl;      // inclusive block total
}

// ---------------- scan C: block only needs SUM of earlier bsums (reduce) ----
__global__ void scanC_kernel(int* __restrict__ offs, const int* __restrict__ bsums, int total) {
    __shared__ int part[4];
    __shared__ int pref;
    int t = threadIdx.x, lane = t & 31, wid = t >> 5;
    if (t < 128) {
        int v = (t < blockIdx.x) ? bsums[t] : 0;        // blockIdx.x <= 97 < 128
#pragma unroll
        for (int d = 16; d > 0; d >>= 1) v += __shfl_down_sync(0xffffffffu, v, d);
        if (lane == 0) part[wid] = v;
    }
    __syncthreads();
    if (t == 0) pref = part[0] + part[1] + part[2] + part[3];
    __syncthreads();
    int i = blockIdx.x * SCAN_B + t;
    if (i < N_NODES) offs[i] += pref;
    if (i == 0) offs[N_NODES] = total;
}

// ---------------- scatter COO -> CSR: float4/int4-vectorized, packed payload -
// MODE 0 (x):   col < 1024   -> p = (col<<16) | fp16(val) bits
// MODE 1 (adj): col < 2^17, val in [0,1) -> p = (col<<15) | round(val*32768) clamped
template <int MODE>
__global__ void scatter_kernel(const int4* __restrict__ rows4, const int4* __restrict__ cols4,
                               const float4* __restrict__ vals4,
                               const int* __restrict__ offs, int* __restrict__ cnt,
                               int* __restrict__ cdata, int n4) {
    int i = blockIdx.x * blockDim.x + threadIdx.x;
    if (i >= n4) return;
    int4   r = __ldcs(&rows4[i]);
    int4   c = __ldcs(&cols4[i]);
    float4 v = __ldcs(&vals4[i]);
#define SCAT_ONE(RR, CC, VV)                                                     \
    {                                                                            \
        int p = offs[(RR)] + atomicSub(&cnt[(RR)], 1) - 1;                       \
        int packed;                                                              \
        if (MODE == 0) {                                                         \
            packed = ((CC) << 16) | (int)__half_as_ushort(__float2half_rn(VV));  \
        } else {                                                                 \
            int q = __float2int_rn((VV) * 32768.f);                              \
            q = min(q, 32767);                                                   \
            packed = ((CC) << 15) | q;                                           \
        }                                                                        \
        cdata[p] = packed;                                                       \
    }
    SCAT_ONE(r.x, c.x, v.x)
    SCAT_ONE(r.y, c.y, v.y)
    SCAT_ONE(r.z, c.z, v.z)
    SCAT_ONE(r.w, c.w, v.w)
#undef SCAT_ONE
}

// ---------------- SpMM1 step: uniform scalar payload load (no shfl) ---------
#define SPMM1_STEP(IDX)                                                          \
    {                                                                            \
        int p = __ldg(&cdata[(IDX)]);   /* all lanes same addr -> broadcast */   \
        int cc = ((unsigned)p) >> 16;                                            \
        unsigned short vh = (unsigned short)(p & 0xffff);                        \
        int4 wv = __ldg(reinterpret_cast<const int4*>(Wh + (size_t)cc * OUT_DIM) + lane); \
        fma_h2(a0, a1, wv.x, vh);                                                \
        fma_h2(a2, a3, wv.y, vh);                                                \
        fma_h2(a4, a5, wv.z, vh);                                                \
        fma_h2(a6, a7, wv.w, vh);                                                \
    }

// ---------------- SpMM1: warp per row (frozen from R13) ----------------------
__global__ void __launch_bounds__(256, 8)
spmm1_kernel(const int* __restrict__ offs, const int* __restrict__ cdata,
             const __half* __restrict__ Wh, __half* __restrict__ xw) {
    int warp = (blockIdx.x * blockDim.x + threadIdx.x) >> 5;
    int lane = threadIdx.x & 31;
    if (warp >= N_NODES) return;

    int beg = offs[warp];
    int end = offs[warp + 1];

    float a0 = 0.f, a1 = 0.f, a2 = 0.f, a3 = 0.f;
    float a4 = 0.f, a5 = 0.f, a6 = 0.f, a7 = 0.f;

    int base = beg;
    for (; base + 32 <= end; base += 32) {
#pragma unroll
        for (int t = 0; t < 32; t++) SPMM1_STEP(base + t)
    }
    for (; base < end; base++) SPMM1_STEP(base)

    int4 o;
    __half2 h0 = __floats2half2_rn(a0, a1);
    __half2 h1 = __floats2half2_rn(a2, a3);
    __half2 h2 = __floats2half2_rn(a4, a5);
    __half2 h3 = __floats2half2_rn(a6, a7);
    o.x = *reinterpret_cast<int*>(&h0);
    o.y = *reinterpret_cast<int*>(&h1);
    o.z = *reinterpret_cast<int*>(&h2);
    o.w = *reinterpret_cast<int*>(&h3);
    reinterpret_cast<int4*>(xw + (size_t)warp * OUT_DIM)[lane] = o;
}

// ---------------- SpMM2 step: uniform scalar payload load (no shfl) ---------
#define SPMM2_STEP(IDX)                                                          \
    {                                                                            \
        int p = __ldg(&cdata[(IDX)]);                                            \
        int cc = ((unsigned)p) >> 15;                                            \
        float vv = (float)(p & 0x7fff) * QINV;                                   \
        int4 wv = __ldg(reinterpret_cast<const int4*>(xw + (size_t)cc * OUT_DIM) + lane); \
        float2 f0 = __half22float2(*reinterpret_cast<__half2*>(&wv.x));          \
        float2 f1 = __half22float2(*reinterpret_cast<__half2*>(&wv.y));          \
        float2 f2 = __half22float2(*reinterpret_cast<__half2*>(&wv.z));          \
        float2 f3 = __half22float2(*reinterpret_cast<__half2*>(&wv.w));          \
        a0 = fmaf(vv, f0.x, a0); a1 = fmaf(vv, f0.y, a1);                        \
        a2 = fmaf(vv, f1.x, a2); a3 = fmaf(vv, f1.y, a3);                        \
        a4 = fmaf(vv, f2.x, a4); a5 = fmaf(vv, f2.y, a5);                        \
        a6 = fmaf(vv, f3.x, a6); a7 = fmaf(vv, f3.y, a7);                        \
    }

// ---------------- SpMM2 + ReLU (frozen from R13) ------------------------------
__global__ void __launch_bounds__(256, 8)
spmm2_kernel(const int* __restrict__ offs, const int* __restrict__ cdata,
             const __half* __restrict__ xw, float* __restrict__ out) {
    int warp = (blockIdx.x * blockDim.x + threadIdx.x) >> 5;
    int lane = threadIdx.x & 31;
    if (warp >= N_NODES) return;

    int beg = offs[warp];
    int end = offs[warp + 1];

    float a0 = 0.f, a1 = 0.f, a2 = 0.f, a3 = 0.f;
    float a4 = 0.f, a5 = 0.f, a6 = 0.f, a7 = 0.f;

    const float QINV = 1.f / 32768.f;

    int base = beg;
    for (; base + 32 <= end; base += 32) {
#pragma unroll
        for (int t = 0; t < 32; t++) SPMM2_STEP(base + t)
    }
    for (; base < end; base++) SPMM2_STEP(base)

    float4* d = reinterpret_cast<float4*>(out + (size_t)warp * OUT_DIM) + lane * 2;
    __stcs(d,     make_float4(fmaxf(a0, 0.f), fmaxf(a1, 0.f), fmaxf(a2, 0.f), fmaxf(a3, 0.f)));
    __stcs(d + 1, make_float4(fmaxf(a4, 0.f), fmaxf(a5, 0.f), fmaxf(a6, 0.f), fmaxf(a7, 0.f)));
}

// ---------------------------------------------------------------------------
extern "C" void kernel_launch(void* const* d_in, const int* in_sizes, int n_in,
                              void* d_out, int out_size) {
    const int*   x_rows   = (const int*)  d_in[0];
    const int*   x_cols   = (const int*)  d_in[1];
    const float* x_vals   = (const float*)d_in[2];
    const int*   adj_rows = (const int*)  d_in[3];
    const int*   adj_cols = (const int*)  d_in[4];
    const float* adj_vals = (const float*)d_in[5];
    const float* W        = (const float*)d_in[6];
    float*       out      = (float*)d_out;

    __half *xw, *Wh; int *cntx, *cnta, *ox, *oa, *bx, *ba, *cx, *ca;
    cudaGetSymbolAddress((void**)&xw,   g_xw);
    cudaGetSymbolAddress((void**)&Wh,   g_wh);
    cudaGetSymbolAddress((void**)&cntx, g_counts_x);
    cudaGetSymbolAddress((void**)&cnta, g_counts_a);
    cudaGetSymbolAddress((void**)&ox,   g_offs_x);
    cudaGetSymbolAddress((void**)&oa,   g_offs_a);
    cudaGetSymbolAddress((void**)&bx,   g_bsums_x);
    cudaGetSymbolAddress((void**)&ba,   g_bsums_a);
    cudaGetSymbolAddress((void**)&cx,   g_cx);
    cudaGetSymbolAddress((void**)&ca,   g_ca);

    // Side stream + events: created once on first (uncaptured) call, reused.
    static cudaStream_t s2 = nullptr;
    static cudaEvent_t  evFork = nullptr, evJoin = nullptr, evW = nullptr;
    if (s2 == nullptr) {
        cudaStreamCreateWithFlags(&s2, cudaStreamNonBlocking);
        cudaEventCreateWithFlags(&evFork, cudaEventDisableTiming);
        cudaEventCreateWithFlags(&evJoin, cudaEventDisableTiming);
        cudaEventCreateWithFlags(&evW,    cudaEventDisableTiming);
    }

    const int n4        = NNZ_X / 4;                       // 800000
    const int n4_blocks = (n4 + 255) / 256;

    // ---- fork (counters are self-zeroed; no zero pass needed) ----
    cudaEventRecord(evFork, 0);
    cudaStreamWaitEvent(s2, evFork, 0);

    // ---- chain B (W convert + adj build) on side stream ----
    wcvt_kernel<<<(IN_DIM * OUT_DIM / 2 + 255) / 256, 256, 0, s2>>>(W, Wh);
    cudaEventRecord(evW, s2);                       // spmm1 depends on Wh
    hist_kernel<<<n4_blocks, 256, 0, s2>>>((const int4*)adj_rows, cnta, n4);
    scanA_kernel<<<N_SCANBLK, SCAN_B, 0, s2>>>(cnta, oa, ba);
    scanC_kernel<<<N_SCANBLK, SCAN_B, 0, s2>>>(oa, ba, NNZ_ADJ);
    scatter_kernel<1><<<n4_blocks, 256, 0, s2>>>((const int4*)adj_rows, (const int4*)adj_cols,
                                                 (const float4*)adj_vals, oa, cnta, ca, n4);
    cudaEventRecord(evJoin, s2);

    // ---- chain A (x build + spmm1) on main stream ----
    hist_kernel<<<n4_blocks, 256>>>((const int4*)x_rows, cntx, n4);
    scanA_kernel<<<N_SCANBLK, SCAN_B>>>(cntx, ox, bx);
    scanC_kernel<<<N_SCANBLK, SCAN_B>>>(ox, bx, NNZ_X);
    scatter_kernel<0><<<n4_blocks, 256>>>((const int4*)x_rows, (const int4*)x_cols,
                                          (const float4*)x_vals, ox, cntx, cx, n4);

    cudaStreamWaitEvent(0, evW, 0);                 // ensure Wh ready
    const int spmm_blocks = (N_NODES * 32 + 255) / 256;   // warp per row
    spmm1_kernel<<<spmm_blocks, 256>>>(ox, cx, Wh, xw);

    // ---- join, then SpMM2 + ReLU ----
    cudaStreamWaitEvent(0, evJoin, 0);
    spmm2_kernel<<<spmm_blocks, 256>>>(oa, ca, xw, out);
}